// round 1
// baseline (speedup 1.0000x reference)
#include <cuda_runtime.h>
#include <cstdint>
#include <cstddef>

// Problem constants (fixed shapes for this problem)
#define HDIM 2048
#define FDIM 7168
#define NE   8
#define TMAX 4096

// ---------------- device scratch (allocation-free rule: __device__ globals) ---
__device__ int   g_cnt[NE];
__device__ int   g_tok[NE * TMAX];
__device__ float g_wt [NE * TMAX];
__device__ float g_h  [(size_t)NE * TMAX * FDIM];   // ~940 MB, fine on GB300

// ---------------- helpers ----------------------------------------------------
__device__ __forceinline__ uint32_t f2tf(float f) {
    uint32_t u;
    asm("cvt.rna.tf32.f32 %0, %1;" : "=r"(u) : "f"(f));
    return u;
}

__device__ __forceinline__ void mma_tf32(float c[4], const uint32_t a[4], const uint32_t b[2]) {
    asm volatile(
        "mma.sync.aligned.m16n8k8.row.col.f32.tf32.tf32.f32 "
        "{%0,%1,%2,%3}, {%4,%5,%6,%7}, {%8,%9}, {%0,%1,%2,%3};"
        : "+f"(c[0]), "+f"(c[1]), "+f"(c[2]), "+f"(c[3])
        : "r"(a[0]), "r"(a[1]), "r"(a[2]), "r"(a[3]), "r"(b[0]), "r"(b[1]));
}

__device__ __forceinline__ float silu_f(float x) {
    return x / (1.0f + __expf(-x));
}

// ---------------- kernel 0: zero out + counters ------------------------------
__global__ void zero_kernel(float* __restrict__ out, int n) {
    int idx = blockIdx.x * blockDim.x + threadIdx.x;
    if (idx < NE) g_cnt[idx] = 0;
    for (int i = idx; i < n; i += gridDim.x * blockDim.x) out[i] = 0.0f;
}

// ---------------- kernel 1: gating (top-2) + dispatch lists ------------------
__global__ void gate_kernel(const float* __restrict__ X, const float* __restrict__ GW) {
    const int t = blockIdx.x;
    __shared__ float xs[HDIM];
    __shared__ float logits[NE];

    const int tid = threadIdx.x;
    for (int i = tid; i < HDIM; i += 256) xs[i] = X[(size_t)t * HDIM + i];
    __syncthreads();

    const int warp = tid >> 5, lane = tid & 31;
    if (warp < NE) {
        const float* gw = GW + (size_t)warp * HDIM;
        float s = 0.0f;
        for (int i = lane; i < HDIM; i += 32) s += xs[i] * gw[i];
        #pragma unroll
        for (int o = 16; o; o >>= 1) s += __shfl_xor_sync(0xffffffffu, s, o);
        if (lane == 0) logits[warp] = s;
    }
    __syncthreads();

    if (tid == 0) {
        int i0 = 0; float l0 = logits[0];
        #pragma unroll
        for (int i = 1; i < NE; i++) if (logits[i] > l0) { l0 = logits[i]; i0 = i; }
        int i1 = -1; float l1 = -1e30f;
        #pragma unroll
        for (int i = 0; i < NE; i++) if (i != i0 && logits[i] > l1) { l1 = logits[i]; i1 = i; }
        // normalized top-2 softmax weights: p0/(p0+p1) = 1/(1+exp(l1-l0))
        float w0 = 1.0f / (1.0f + __expf(l1 - l0));
        float w1 = 1.0f - w0;
        int p0 = atomicAdd(&g_cnt[i0], 1);
        g_tok[i0 * TMAX + p0] = t; g_wt[i0 * TMAX + p0] = w0;
        int p1 = atomicAdd(&g_cnt[i1], 1);
        g_tok[i1 * TMAX + p1] = t; g_wt[i1 * TMAX + p1] = w1;
    }
}

// ---------------- kernel 2: grouped GEMM1  h = silu(X@w1^T) * (X@w3^T) -------
// tile 128(M) x 64(N:F) x 32(K), 8 warps in 4(M) x 2(N), warp tile 32x32
__global__ __launch_bounds__(256) void gemm1_kernel(
    const float* __restrict__ X,
    const float* __restrict__ W1,
    const float* __restrict__ W3)
{
    const int e   = blockIdx.z;
    const int cnt = g_cnt[e];
    const int m0  = blockIdx.y * 128;
    if (m0 >= cnt) return;
    const int n0  = blockIdx.x * 64;

    __shared__ uint32_t As [128][36];
    __shared__ uint32_t B1s[64][36];
    __shared__ uint32_t B3s[64][36];

    const int tid  = threadIdx.x;
    const int lane = tid & 31, warp = tid >> 5;
    const int wm = warp >> 1, wn = warp & 1;
    const int g  = lane >> 2, tg = lane & 3;

    float acc1[2][4][4] = {};
    float acc3[2][4][4] = {};

    const int*   tokp = g_tok + e * TMAX + m0;
    const float* W1e  = W1 + (size_t)e * FDIM * HDIM + (size_t)n0 * HDIM;
    const float* W3e  = W3 + (size_t)e * FDIM * HDIM + (size_t)n0 * HDIM;

    const int ak4 = (tid & 7) * 4;
    int arow[4]; int atok[4];
    #pragma unroll
    for (int i = 0; i < 4; i++) {
        arow[i] = (tid + i * 256) >> 3;            // 0..127
        int row = m0 + arow[i];
        atok[i] = (row < cnt) ? tokp[arow[i]] : 0; // clamp invalid rows to token 0
    }
    int brow[2];
    #pragma unroll
    for (int i = 0; i < 2; i++) brow[i] = (tid + i * 256) >> 3; // 0..63

    for (int k0 = 0; k0 < HDIM; k0 += 32) {
        #pragma unroll
        for (int i = 0; i < 4; i++) {
            float4 v = *reinterpret_cast<const float4*>(X + (size_t)atok[i] * HDIM + k0 + ak4);
            As[arow[i]][ak4 + 0] = f2tf(v.x);
            As[arow[i]][ak4 + 1] = f2tf(v.y);
            As[arow[i]][ak4 + 2] = f2tf(v.z);
            As[arow[i]][ak4 + 3] = f2tf(v.w);
        }
        #pragma unroll
        for (int i = 0; i < 2; i++) {
            int r = brow[i];
            float4 v1 = *reinterpret_cast<const float4*>(W1e + (size_t)r * HDIM + k0 + ak4);
            float4 v3 = *reinterpret_cast<const float4*>(W3e + (size_t)r * HDIM + k0 + ak4);
            B1s[r][ak4 + 0] = f2tf(v1.x); B1s[r][ak4 + 1] = f2tf(v1.y);
            B1s[r][ak4 + 2] = f2tf(v1.z); B1s[r][ak4 + 3] = f2tf(v1.w);
            B3s[r][ak4 + 0] = f2tf(v3.x); B3s[r][ak4 + 1] = f2tf(v3.y);
            B3s[r][ak4 + 2] = f2tf(v3.z); B3s[r][ak4 + 3] = f2tf(v3.w);
        }
        __syncthreads();

        #pragma unroll
        for (int kk = 0; kk < 32; kk += 8) {
            uint32_t a[2][4];
            #pragma unroll
            for (int mi = 0; mi < 2; mi++) {
                int mr = wm * 32 + mi * 16;
                a[mi][0] = As[mr + g    ][kk + tg    ];
                a[mi][1] = As[mr + g + 8][kk + tg    ];
                a[mi][2] = As[mr + g    ][kk + tg + 4];
                a[mi][3] = As[mr + g + 8][kk + tg + 4];
            }
            #pragma unroll
            for (int ni = 0; ni < 4; ni++) {
                int nc = wn * 32 + ni * 8;
                uint32_t b1[2] = { B1s[nc + g][kk + tg], B1s[nc + g][kk + tg + 4] };
                uint32_t b3[2] = { B3s[nc + g][kk + tg], B3s[nc + g][kk + tg + 4] };
                #pragma unroll
                for (int mi = 0; mi < 2; mi++) {
                    mma_tf32(acc1[mi][ni], a[mi], b1);
                    mma_tf32(acc3[mi][ni], a[mi], b3);
                }
            }
        }
        __syncthreads();
    }

    // epilogue: h = silu(acc1) * acc3 -> g_h
    #pragma unroll
    for (int mi = 0; mi < 2; mi++) {
        int mr = m0 + wm * 32 + mi * 16;
        int r0 = mr + g, r1 = mr + g + 8;
        #pragma unroll
        for (int ni = 0; ni < 4; ni++) {
            int c = n0 + wn * 32 + ni * 8 + tg * 2;
            if (r0 < cnt) {
                size_t base = ((size_t)e * TMAX + r0) * FDIM + c;
                g_h[base    ] = silu_f(acc1[mi][ni][0]) * acc3[mi][ni][0];
                g_h[base + 1] = silu_f(acc1[mi][ni][1]) * acc3[mi][ni][1];
            }
            if (r1 < cnt) {
                size_t base = ((size_t)e * TMAX + r1) * FDIM + c;
                g_h[base    ] = silu_f(acc1[mi][ni][2]) * acc3[mi][ni][2];
                g_h[base + 1] = silu_f(acc1[mi][ni][3]) * acc3[mi][ni][3];
            }
        }
    }
}

// ---------------- kernel 3: grouped GEMM2  out += wt * (h @ w2^T) ------------
// tile 128(M) x 128(N:H) x 32(K:F), 8 warps 4(M) x 2(N), warp tile 32x64
__global__ __launch_bounds__(256) void gemm2_kernel(
    const float* __restrict__ W2, float* __restrict__ out)
{
    const int e   = blockIdx.z;
    const int cnt = g_cnt[e];
    const int m0  = blockIdx.y * 128;
    if (m0 >= cnt) return;
    const int n0  = blockIdx.x * 128;

    __shared__ uint32_t As[128][36];
    __shared__ uint32_t Bs[128][36];

    const int tid  = threadIdx.x;
    const int lane = tid & 31, warp = tid >> 5;
    const int wm = warp & 3, wn = warp >> 2;
    const int g  = lane >> 2, tg = lane & 3;

    float acc[2][8][4] = {};

    const float* Ae  = g_h + ((size_t)e * TMAX + m0) * FDIM;
    const float* W2e = W2 + (size_t)e * HDIM * FDIM + (size_t)n0 * FDIM;
    const int ak4 = (tid & 7) * 4;

    for (int k0 = 0; k0 < FDIM; k0 += 32) {
        #pragma unroll
        for (int i = 0; i < 4; i++) {
            int r = (tid + i * 256) >> 3;   // 0..127
            float4 va = *reinterpret_cast<const float4*>(Ae  + (size_t)r * FDIM + k0 + ak4);
            float4 vb = *reinterpret_cast<const float4*>(W2e + (size_t)r * FDIM + k0 + ak4);
            As[r][ak4 + 0] = f2tf(va.x); As[r][ak4 + 1] = f2tf(va.y);
            As[r][ak4 + 2] = f2tf(va.z); As[r][ak4 + 3] = f2tf(va.w);
            Bs[r][ak4 + 0] = f2tf(vb.x); Bs[r][ak4 + 1] = f2tf(vb.y);
            Bs[r][ak4 + 2] = f2tf(vb.z); Bs[r][ak4 + 3] = f2tf(vb.w);
        }
        __syncthreads();

        #pragma unroll
        for (int kk = 0; kk < 32; kk += 8) {
            uint32_t a[2][4];
            #pragma unroll
            for (int mi = 0; mi < 2; mi++) {
                int mr = wm * 32 + mi * 16;
                a[mi][0] = As[mr + g    ][kk + tg    ];
                a[mi][1] = As[mr + g + 8][kk + tg    ];
                a[mi][2] = As[mr + g    ][kk + tg + 4];
                a[mi][3] = As[mr + g + 8][kk + tg + 4];
            }
            #pragma unroll
            for (int ni = 0; ni < 8; ni++) {
                int nc = wn * 64 + ni * 8;
                uint32_t b[2] = { Bs[nc + g][kk + tg], Bs[nc + g][kk + tg + 4] };
                #pragma unroll
                for (int mi = 0; mi < 2; mi++) {
                    mma_tf32(acc[mi][ni], a[mi], b);
                }
            }
        }
        __syncthreads();
    }

    // epilogue: out[tok] += wt * acc  (exactly 2 commutative adds per element -> deterministic)
    #pragma unroll
    for (int mi = 0; mi < 2; mi++) {
        int mr = m0 + wm * 32 + mi * 16;
        int r0 = mr + g, r1 = mr + g + 8;
        int tok0 = 0, tok1 = 0; float wt0 = 0.0f, wt1 = 0.0f;
        if (r0 < cnt) { tok0 = g_tok[e * TMAX + r0]; wt0 = g_wt[e * TMAX + r0]; }
        if (r1 < cnt) { tok1 = g_tok[e * TMAX + r1]; wt1 = g_wt[e * TMAX + r1]; }
        #pragma unroll
        for (int ni = 0; ni < 8; ni++) {
            int c = n0 + wn * 64 + ni * 8 + tg * 2;
            if (r0 < cnt) {
                atomicAdd(out + (size_t)tok0 * HDIM + c,     wt0 * acc[mi][ni][0]);
                atomicAdd(out + (size_t)tok0 * HDIM + c + 1, wt0 * acc[mi][ni][1]);
            }
            if (r1 < cnt) {
                atomicAdd(out + (size_t)tok1 * HDIM + c,     wt1 * acc[mi][ni][2]);
                atomicAdd(out + (size_t)tok1 * HDIM + c + 1, wt1 * acc[mi][ni][3]);
            }
        }
    }
}

// ---------------- launcher ---------------------------------------------------
extern "C" void kernel_launch(void* const* d_in, const int* in_sizes, int n_in,
                              void* d_out, int out_size) {
    const float* X  = (const float*)d_in[0];
    const float* GW = (const float*)d_in[1];
    const float* W1 = (const float*)d_in[2];
    const float* W2 = (const float*)d_in[3];
    const float* W3 = (const float*)d_in[4];
    float* out = (float*)d_out;

    int T = in_sizes[0] / HDIM;   // 4096
    if (T > TMAX) T = TMAX;

    zero_kernel<<<2048, 256>>>(out, out_size);
    gate_kernel<<<T, 256>>>(X, GW);

    int mt = (T + 127) / 128;
    dim3 grid1(FDIM / 64, mt, NE);
    gemm1_kernel<<<grid1, 256>>>(X, W1, W3);

    dim3 grid2(HDIM / 128, mt, NE);
    gemm2_kernel<<<grid2, 256>>>(W2, out);
}

// round 2
// speedup vs baseline: 1.0865x; 1.0865x over previous
#include <cuda_runtime.h>
#include <cstdint>
#include <cstddef>

// Problem constants (fixed shapes for this problem)
#define HDIM 2048
#define FDIM 7168
#define NE   8
#define TMAX 4096
#define STAGES 3

// ---------------- device scratch (allocation-free rule: __device__ globals) ---
__device__ int   g_cnt[NE];
__device__ int   g_tok[NE * TMAX];
__device__ float g_wt [NE * TMAX];
__device__ float g_h  [(size_t)NE * TMAX * FDIM];

// ---------------- helpers ----------------------------------------------------
__device__ __forceinline__ uint32_t f2tf(float f) {
    uint32_t u;
    asm("cvt.rna.tf32.f32 %0, %1;" : "=r"(u) : "f"(f));
    return u;
}

__device__ __forceinline__ void mma_tf32(float c[4], const uint32_t a[4], const uint32_t b[2]) {
    asm volatile(
        "mma.sync.aligned.m16n8k8.row.col.f32.tf32.tf32.f32 "
        "{%0,%1,%2,%3}, {%4,%5,%6,%7}, {%8,%9}, {%0,%1,%2,%3};"
        : "+f"(c[0]), "+f"(c[1]), "+f"(c[2]), "+f"(c[3])
        : "r"(a[0]), "r"(a[1]), "r"(a[2]), "r"(a[3]), "r"(b[0]), "r"(b[1]));
}

__device__ __forceinline__ float silu_f(float x) {
    return x / (1.0f + __expf(-x));
}

__device__ __forceinline__ void cp16(void* smem, const float* g) {
    uint32_t sa = (uint32_t)__cvta_generic_to_shared(smem);
    asm volatile("cp.async.cg.shared.global [%0], [%1], 16;" :: "r"(sa), "l"(g));
}
#define CP_COMMIT()  asm volatile("cp.async.commit_group;")
#define CP_WAIT(N)   asm volatile("cp.async.wait_group %0;" :: "n"(N))

// ---------------- kernel 0: zero out + counters ------------------------------
__global__ void zero_kernel(float* __restrict__ out, int n) {
    int idx = blockIdx.x * blockDim.x + threadIdx.x;
    if (idx < NE) g_cnt[idx] = 0;
    for (int i = idx; i < n; i += gridDim.x * blockDim.x) out[i] = 0.0f;
}

// ---------------- kernel 1: gating (top-2) + dispatch lists ------------------
__global__ void gate_kernel(const float* __restrict__ X, const float* __restrict__ GW) {
    const int t = blockIdx.x;
    __shared__ float xs[HDIM];
    __shared__ float logits[NE];

    const int tid = threadIdx.x;
    for (int i = tid; i < HDIM; i += 256) xs[i] = X[(size_t)t * HDIM + i];
    __syncthreads();

    const int warp = tid >> 5, lane = tid & 31;
    if (warp < NE) {
        const float* gw = GW + (size_t)warp * HDIM;
        float s = 0.0f;
        for (int i = lane; i < HDIM; i += 32) s += xs[i] * gw[i];
        #pragma unroll
        for (int o = 16; o; o >>= 1) s += __shfl_xor_sync(0xffffffffu, s, o);
        if (lane == 0) logits[warp] = s;
    }
    __syncthreads();

    if (tid == 0) {
        int i0 = 0; float l0 = logits[0];
        #pragma unroll
        for (int i = 1; i < NE; i++) if (logits[i] > l0) { l0 = logits[i]; i0 = i; }
        int i1 = -1; float l1 = -1e30f;
        #pragma unroll
        for (int i = 0; i < NE; i++) if (i != i0 && logits[i] > l1) { l1 = logits[i]; i1 = i; }
        float w0 = 1.0f / (1.0f + __expf(l1 - l0));
        float w1 = 1.0f - w0;
        int p0 = atomicAdd(&g_cnt[i0], 1);
        g_tok[i0 * TMAX + p0] = t; g_wt[i0 * TMAX + p0] = w0;
        int p1 = atomicAdd(&g_cnt[i1], 1);
        g_tok[i1 * TMAX + p1] = t; g_wt[i1 * TMAX + p1] = w1;
    }
}

// ---------------- kernel 2: grouped GEMM1  h = silu(X@w1^T) * (X@w3^T) -------
// tile 128(M) x 64+64(N:F for w1,w3) x 32(K), 3-stage cp.async pipeline
#define SM1_A  (STAGES * 128 * 36)
#define SM1_B  (STAGES * 64 * 36)
#define SMEM1_BYTES ((SM1_A + 2 * SM1_B) * 4)

__global__ __launch_bounds__(256, 1) void gemm1_kernel(
    const float* __restrict__ X,
    const float* __restrict__ W1,
    const float* __restrict__ W3)
{
    const int e   = blockIdx.z;
    const int cnt = g_cnt[e];
    const int m0  = blockIdx.y * 128;
    if (m0 >= cnt) return;
    const int n0  = blockIdx.x * 64;

    extern __shared__ float smem[];
    float* sA  = smem;
    float* sB1 = smem + SM1_A;
    float* sB3 = sB1 + SM1_B;
    #define A1(s,r,c)  sA [((s) * 128 + (r)) * 36 + (c)]
    #define B1(s,r,c)  sB1[((s) * 64  + (r)) * 36 + (c)]
    #define B3(s,r,c)  sB3[((s) * 64  + (r)) * 36 + (c)]

    const int tid  = threadIdx.x;
    const int lane = tid & 31, warp = tid >> 5;
    const int wm = warp >> 1, wn = warp & 1;
    const int g  = lane >> 2, tg = lane & 3;

    float acc1[2][4][4] = {};
    float acc3[2][4][4] = {};

    const int*   tokp = g_tok + e * TMAX + m0;
    const float* W1e  = W1 + (size_t)e * FDIM * HDIM + (size_t)n0 * HDIM;
    const float* W3e  = W3 + (size_t)e * FDIM * HDIM + (size_t)n0 * HDIM;

    const int c4 = (tid & 7) * 4;
    int arow[4]; const float* aptr[4];
    #pragma unroll
    for (int i = 0; i < 4; i++) {
        arow[i] = (tid + i * 256) >> 3;
        int row = m0 + arow[i];
        int tok = (row < cnt) ? tokp[arow[i]] : 0;
        aptr[i] = X + (size_t)tok * HDIM + c4;
    }
    const int brow = tid >> 3;          // 0..31 (tid<256 -> two rows via +32)
    const int nkt = HDIM / 32;

    // ---- load stage macro ----
    #define LOAD1(s, kt) do {                                                   \
        int k0_ = (kt) * 32;                                                    \
        _Pragma("unroll")                                                       \
        for (int i_ = 0; i_ < 4; i_++)                                          \
            cp16(&A1(s, arow[i_], c4), aptr[i_] + k0_);                         \
        cp16(&B1(s, brow,      c4), W1e + (size_t)(brow     ) * HDIM + k0_ + c4);\
        cp16(&B1(s, brow + 32, c4), W1e + (size_t)(brow + 32) * HDIM + k0_ + c4);\
        cp16(&B3(s, brow,      c4), W3e + (size_t)(brow     ) * HDIM + k0_ + c4);\
        cp16(&B3(s, brow + 32, c4), W3e + (size_t)(brow + 32) * HDIM + k0_ + c4);\
    } while (0)

    #pragma unroll
    for (int s = 0; s < STAGES - 1; s++) { LOAD1(s, s); CP_COMMIT(); }

    for (int it = 0; it < nkt; it++) {
        CP_WAIT(STAGES - 2);
        __syncthreads();

        int pf = it + STAGES - 1;
        if (pf < nkt) LOAD1((pf % STAGES), pf);
        CP_COMMIT();

        const int s = it % STAGES;
        #pragma unroll
        for (int kk = 0; kk < 32; kk += 8) {
            uint32_t a[2][4];
            #pragma unroll
            for (int mi = 0; mi < 2; mi++) {
                int mr = wm * 32 + mi * 16;
                a[mi][0] = f2tf(A1(s, mr + g,     kk + tg    ));
                a[mi][1] = f2tf(A1(s, mr + g + 8, kk + tg    ));
                a[mi][2] = f2tf(A1(s, mr + g,     kk + tg + 4));
                a[mi][3] = f2tf(A1(s, mr + g + 8, kk + tg + 4));
            }
            #pragma unroll
            for (int ni = 0; ni < 4; ni++) {
                int nc = wn * 32 + ni * 8;
                uint32_t b1[2] = { f2tf(B1(s, nc + g, kk + tg)), f2tf(B1(s, nc + g, kk + tg + 4)) };
                uint32_t b3[2] = { f2tf(B3(s, nc + g, kk + tg)), f2tf(B3(s, nc + g, kk + tg + 4)) };
                #pragma unroll
                for (int mi = 0; mi < 2; mi++) {
                    mma_tf32(acc1[mi][ni], a[mi], b1);
                    mma_tf32(acc3[mi][ni], a[mi], b3);
                }
            }
        }
        __syncthreads();
    }

    // epilogue: h = silu(acc1) * acc3 -> g_h
    #pragma unroll
    for (int mi = 0; mi < 2; mi++) {
        int mr = m0 + wm * 32 + mi * 16;
        int r0 = mr + g, r1 = mr + g + 8;
        #pragma unroll
        for (int ni = 0; ni < 4; ni++) {
            int c = n0 + wn * 32 + ni * 8 + tg * 2;
            if (r0 < cnt) {
                size_t base = ((size_t)e * TMAX + r0) * FDIM + c;
                g_h[base    ] = silu_f(acc1[mi][ni][0]) * acc3[mi][ni][0];
                g_h[base + 1] = silu_f(acc1[mi][ni][1]) * acc3[mi][ni][1];
            }
            if (r1 < cnt) {
                size_t base = ((size_t)e * TMAX + r1) * FDIM + c;
                g_h[base    ] = silu_f(acc1[mi][ni][2]) * acc3[mi][ni][2];
                g_h[base + 1] = silu_f(acc1[mi][ni][3]) * acc3[mi][ni][3];
            }
        }
    }
}

// ---------------- kernel 3: grouped GEMM2  out += wt * (h @ w2^T) ------------
// tile 128(M) x 128(N:H) x 32(K:F), 3-stage cp.async pipeline
#define SM2_A  (STAGES * 128 * 36)
#define SMEM2_BYTES (2 * SM2_A * 4)

__global__ __launch_bounds__(256, 1) void gemm2_kernel(
    const float* __restrict__ W2, float* __restrict__ out)
{
    const int e   = blockIdx.z;
    const int cnt = g_cnt[e];
    const int m0  = blockIdx.y * 128;
    if (m0 >= cnt) return;
    const int n0  = blockIdx.x * 128;

    extern __shared__ float smem[];
    float* sA = smem;
    float* sB = smem + SM2_A;
    #define A2(s,r,c)  sA[((s) * 128 + (r)) * 36 + (c)]
    #define B2(s,r,c)  sB[((s) * 128 + (r)) * 36 + (c)]

    const int tid  = threadIdx.x;
    const int lane = tid & 31, warp = tid >> 5;
    const int wm = warp & 3, wn = warp >> 2;
    const int g  = lane >> 2, tg = lane & 3;

    float acc[2][8][4] = {};

    const float* Ae  = g_h + ((size_t)e * TMAX + m0) * FDIM;
    const float* W2e = W2 + (size_t)e * HDIM * FDIM + (size_t)n0 * FDIM;
    const int c4 = (tid & 7) * 4;
    const int lrow = tid >> 3;   // 0..31, rows via +32*i
    const int nkt = FDIM / 32;

    #define LOAD2(s, kt) do {                                                    \
        int k0_ = (kt) * 32;                                                     \
        _Pragma("unroll")                                                        \
        for (int i_ = 0; i_ < 4; i_++) {                                         \
            int r_ = lrow + i_ * 32;                                             \
            cp16(&A2(s, r_, c4), Ae  + (size_t)r_ * FDIM + k0_ + c4);            \
            cp16(&B2(s, r_, c4), W2e + (size_t)r_ * FDIM + k0_ + c4);            \
        }                                                                        \
    } while (0)

    #pragma unroll
    for (int s = 0; s < STAGES - 1; s++) { LOAD2(s, s); CP_COMMIT(); }

    for (int it = 0; it < nkt; it++) {
        CP_WAIT(STAGES - 2);
        __syncthreads();

        int pf = it + STAGES - 1;
        if (pf < nkt) LOAD2((pf % STAGES), pf);
        CP_COMMIT();

        const int s = it % STAGES;
        #pragma unroll
        for (int kk = 0; kk < 32; kk += 8) {
            uint32_t a[2][4];
            #pragma unroll
            for (int mi = 0; mi < 2; mi++) {
                int mr = wm * 32 + mi * 16;
                a[mi][0] = f2tf(A2(s, mr + g,     kk + tg    ));
                a[mi][1] = f2tf(A2(s, mr + g + 8, kk + tg    ));
                a[mi][2] = f2tf(A2(s, mr + g,     kk + tg + 4));
                a[mi][3] = f2tf(A2(s, mr + g + 8, kk + tg + 4));
            }
            #pragma unroll
            for (int ni = 0; ni < 8; ni++) {
                int nc = wn * 64 + ni * 8;
                uint32_t b[2] = { f2tf(B2(s, nc + g, kk + tg)), f2tf(B2(s, nc + g, kk + tg + 4)) };
                #pragma unroll
                for (int mi = 0; mi < 2; mi++) {
                    mma_tf32(acc[mi][ni], a[mi], b);
                }
            }
        }
        __syncthreads();
    }

    // epilogue: out[tok] += wt * acc (exactly 2 commutative adds/elem -> deterministic)
    #pragma unroll
    for (int mi = 0; mi < 2; mi++) {
        int mr = m0 + wm * 32 + mi * 16;
        int r0 = mr + g, r1 = mr + g + 8;
        int tok0 = 0, tok1 = 0; float wt0 = 0.0f, wt1 = 0.0f;
        if (r0 < cnt) { tok0 = g_tok[e * TMAX + r0]; wt0 = g_wt[e * TMAX + r0]; }
        if (r1 < cnt) { tok1 = g_tok[e * TMAX + r1]; wt1 = g_wt[e * TMAX + r1]; }
        #pragma unroll
        for (int ni = 0; ni < 8; ni++) {
            int c = n0 + wn * 64 + ni * 8 + tg * 2;
            if (r0 < cnt) {
                atomicAdd(out + (size_t)tok0 * HDIM + c,     wt0 * acc[mi][ni][0]);
                atomicAdd(out + (size_t)tok0 * HDIM + c + 1, wt0 * acc[mi][ni][1]);
            }
            if (r1 < cnt) {
                atomicAdd(out + (size_t)tok1 * HDIM + c,     wt1 * acc[mi][ni][2]);
                atomicAdd(out + (size_t)tok1 * HDIM + c + 1, wt1 * acc[mi][ni][3]);
            }
        }
    }
}

// ---------------- launcher ---------------------------------------------------
extern "C" void kernel_launch(void* const* d_in, const int* in_sizes, int n_in,
                              void* d_out, int out_size) {
    const float* X  = (const float*)d_in[0];
    const float* GW = (const float*)d_in[1];
    const float* W1 = (const float*)d_in[2];
    const float* W2 = (const float*)d_in[3];
    const float* W3 = (const float*)d_in[4];
    float* out = (float*)d_out;

    int T = in_sizes[0] / HDIM;   // 4096
    if (T > TMAX) T = TMAX;

    cudaFuncSetAttribute(gemm1_kernel, cudaFuncAttributeMaxDynamicSharedMemorySize, SMEM1_BYTES);
    cudaFuncSetAttribute(gemm2_kernel, cudaFuncAttributeMaxDynamicSharedMemorySize, SMEM2_BYTES);

    zero_kernel<<<2048, 256>>>(out, out_size);
    gate_kernel<<<T, 256>>>(X, GW);

    int mt = (T + 127) / 128;
    dim3 grid1(FDIM / 64, mt, NE);
    gemm1_kernel<<<grid1, 256, SMEM1_BYTES>>>(X, W1, W3);

    dim3 grid2(HDIM / 128, mt, NE);
    gemm2_kernel<<<grid2, 256, SMEM2_BYTES>>>(W2, out);
}

// round 3
// speedup vs baseline: 1.2541x; 1.1543x over previous
#include <cuda_runtime.h>
#include <cstdint>
#include <cstddef>

#define HDIM 2048
#define FDIM 7168
#define NE   8
#define TMAX 4096
#define STAGES 3
#define WELEM (NE * FDIM * HDIM)   // 117,440,512 elements per weight tensor

// ---------------- device scratch (allocation-free rule: __device__ globals) ---
__device__ int   g_cnt[NE];
__device__ int   g_tok[NE * TMAX];
__device__ float g_wt [NE * TMAX];
__device__ float g_h  [(size_t)NE * TMAX * FDIM];
__device__ float g_w1t[WELEM];
__device__ float g_w2t[WELEM];
__device__ float g_w3t[WELEM];
__device__ float g_xt [(size_t)TMAX * HDIM];

// ---------------- helpers ----------------------------------------------------
__device__ __forceinline__ uint32_t f2tf(float f) {
    uint32_t u;
    asm("cvt.rna.tf32.f32 %0, %1;" : "=r"(u) : "f"(f));
    return u;
}
__device__ __forceinline__ float f2tf_f(float f) {
    return __uint_as_float(f2tf(f));
}

__device__ __forceinline__ void mma_tf32(float c[4], const uint32_t a[4], const uint32_t b[2]) {
    asm volatile(
        "mma.sync.aligned.m16n8k8.row.col.f32.tf32.tf32.f32 "
        "{%0,%1,%2,%3}, {%4,%5,%6,%7}, {%8,%9}, {%0,%1,%2,%3};"
        : "+f"(c[0]), "+f"(c[1]), "+f"(c[2]), "+f"(c[3])
        : "r"(a[0]), "r"(a[1]), "r"(a[2]), "r"(a[3]), "r"(b[0]), "r"(b[1]));
}

__device__ __forceinline__ float silu_f(float x) {
    return x / (1.0f + __expf(-x));
}

__device__ __forceinline__ void cp16(void* smem, const float* g) {
    uint32_t sa = (uint32_t)__cvta_generic_to_shared(smem);
    asm volatile("cp.async.cg.shared.global [%0], [%1], 16;" :: "r"(sa), "l"(g));
}
#define CP_COMMIT()  asm volatile("cp.async.commit_group;")
#define CP_WAIT(N)   asm volatile("cp.async.wait_group %0;" :: "n"(N))

// ---------------- kernel 0: zero out + counters ------------------------------
__global__ void zero_kernel(float* __restrict__ out, int n) {
    int idx = blockIdx.x * blockDim.x + threadIdx.x;
    if (idx < NE) g_cnt[idx] = 0;
    for (int i = idx; i < n; i += gridDim.x * blockDim.x) out[i] = 0.0f;
}

// ---------------- kernel 0b: tf32-RNA pre-round into scratch ------------------
__global__ void convert_kernel(const float* __restrict__ src, float* __restrict__ dst, int n4) {
    int idx = blockIdx.x * blockDim.x + threadIdx.x;
    const float4* s4 = (const float4*)src;
    float4* d4 = (float4*)dst;
    for (int i = idx; i < n4; i += gridDim.x * blockDim.x) {
        float4 v = s4[i];
        v.x = f2tf_f(v.x); v.y = f2tf_f(v.y); v.z = f2tf_f(v.z); v.w = f2tf_f(v.w);
        d4[i] = v;
    }
}

// ---------------- kernel 1: gating (top-2) + dispatch lists ------------------
__global__ void gate_kernel(const float* __restrict__ X, const float* __restrict__ GW) {
    const int t = blockIdx.x;
    __shared__ float xs[HDIM];
    __shared__ float logits[NE];

    const int tid = threadIdx.x;
    for (int i = tid; i < HDIM; i += 256) xs[i] = X[(size_t)t * HDIM + i];
    __syncthreads();

    const int warp = tid >> 5, lane = tid & 31;
    if (warp < NE) {
        const float* gw = GW + (size_t)warp * HDIM;
        float s = 0.0f;
        for (int i = lane; i < HDIM; i += 32) s += xs[i] * gw[i];
        #pragma unroll
        for (int o = 16; o; o >>= 1) s += __shfl_xor_sync(0xffffffffu, s, o);
        if (lane == 0) logits[warp] = s;
    }
    __syncthreads();

    if (tid == 0) {
        int i0 = 0; float l0 = logits[0];
        #pragma unroll
        for (int i = 1; i < NE; i++) if (logits[i] > l0) { l0 = logits[i]; i0 = i; }
        int i1 = -1; float l1 = -1e30f;
        #pragma unroll
        for (int i = 0; i < NE; i++) if (i != i0 && logits[i] > l1) { l1 = logits[i]; i1 = i; }
        float w0 = 1.0f / (1.0f + __expf(l1 - l0));
        float w1 = 1.0f - w0;
        int p0 = atomicAdd(&g_cnt[i0], 1);
        g_tok[i0 * TMAX + p0] = t; g_wt[i0 * TMAX + p0] = w0;
        int p1 = atomicAdd(&g_cnt[i1], 1);
        g_tok[i1 * TMAX + p1] = t; g_wt[i1 * TMAX + p1] = w1;
    }
}

// ---------------- kernel 2: grouped GEMM1  h = silu(X@w1^T) * (X@w3^T) -------
// tile 128(M) x 64+64(N) x 32(K), 3-stage cp.async pipeline, operands pre-rounded
#define SM1_A  (STAGES * 128 * 36)
#define SM1_B  (STAGES * 64 * 36)
#define SMEM1_BYTES ((SM1_A + 2 * SM1_B) * 4)

__global__ __launch_bounds__(256, 2) void gemm1_kernel(
    const float* __restrict__ X,
    const float* __restrict__ W1,
    const float* __restrict__ W3)
{
    const int e   = blockIdx.z;
    const int cnt = g_cnt[e];
    const int m0  = blockIdx.y * 128;
    if (m0 >= cnt) return;
    const int n0  = blockIdx.x * 64;

    extern __shared__ float smem[];
    float* sA  = smem;
    float* sB1 = smem + SM1_A;
    float* sB3 = sB1 + SM1_B;
    #define A1(s,r,c)  sA [((s) * 128 + (r)) * 36 + (c)]
    #define B1(s,r,c)  sB1[((s) * 64  + (r)) * 36 + (c)]
    #define B3(s,r,c)  sB3[((s) * 64  + (r)) * 36 + (c)]

    const int tid  = threadIdx.x;
    const int lane = tid & 31, warp = tid >> 5;
    const int wm = warp >> 1, wn = warp & 1;
    const int g  = lane >> 2, tg = lane & 3;

    float acc1[2][4][4] = {};
    float acc3[2][4][4] = {};

    const int*   tokp = g_tok + e * TMAX + m0;
    const float* W1e  = W1 + (size_t)e * FDIM * HDIM + (size_t)n0 * HDIM;
    const float* W3e  = W3 + (size_t)e * FDIM * HDIM + (size_t)n0 * HDIM;

    const int c4 = (tid & 7) * 4;
    int arow[4]; const float* aptr[4];
    #pragma unroll
    for (int i = 0; i < 4; i++) {
        arow[i] = (tid + i * 256) >> 3;
        int row = m0 + arow[i];
        int tok = (row < cnt) ? tokp[arow[i]] : 0;
        aptr[i] = X + (size_t)tok * HDIM + c4;
    }
    const int brow = tid >> 3;
    const int nkt = HDIM / 32;

    #define LOAD1(s, kt) do {                                                   \
        int k0_ = (kt) * 32;                                                    \
        _Pragma("unroll")                                                       \
        for (int i_ = 0; i_ < 4; i_++)                                          \
            cp16(&A1(s, arow[i_], c4), aptr[i_] + k0_);                         \
        cp16(&B1(s, brow,      c4), W1e + (size_t)(brow     ) * HDIM + k0_ + c4);\
        cp16(&B1(s, brow + 32, c4), W1e + (size_t)(brow + 32) * HDIM + k0_ + c4);\
        cp16(&B3(s, brow,      c4), W3e + (size_t)(brow     ) * HDIM + k0_ + c4);\
        cp16(&B3(s, brow + 32, c4), W3e + (size_t)(brow + 32) * HDIM + k0_ + c4);\
    } while (0)

    #pragma unroll
    for (int s = 0; s < STAGES - 1; s++) { LOAD1(s, s); CP_COMMIT(); }

    for (int it = 0; it < nkt; it++) {
        CP_WAIT(STAGES - 2);
        __syncthreads();

        int pf = it + STAGES - 1;
        if (pf < nkt) LOAD1((pf % STAGES), pf);
        CP_COMMIT();

        const int s = it % STAGES;
        #pragma unroll
        for (int kk = 0; kk < 32; kk += 8) {
            uint32_t a[2][4];
            #pragma unroll
            for (int mi = 0; mi < 2; mi++) {
                int mr = wm * 32 + mi * 16;
                a[mi][0] = __float_as_uint(A1(s, mr + g,     kk + tg    ));
                a[mi][1] = __float_as_uint(A1(s, mr + g + 8, kk + tg    ));
                a[mi][2] = __float_as_uint(A1(s, mr + g,     kk + tg + 4));
                a[mi][3] = __float_as_uint(A1(s, mr + g + 8, kk + tg + 4));
            }
            #pragma unroll
            for (int ni = 0; ni < 4; ni++) {
                int nc = wn * 32 + ni * 8;
                uint32_t b1[2] = { __float_as_uint(B1(s, nc + g, kk + tg)),
                                   __float_as_uint(B1(s, nc + g, kk + tg + 4)) };
                uint32_t b3[2] = { __float_as_uint(B3(s, nc + g, kk + tg)),
                                   __float_as_uint(B3(s, nc + g, kk + tg + 4)) };
                #pragma unroll
                for (int mi = 0; mi < 2; mi++) {
                    mma_tf32(acc1[mi][ni], a[mi], b1);
                    mma_tf32(acc3[mi][ni], a[mi], b3);
                }
            }
        }
        __syncthreads();
    }

    // epilogue: h = tf32_round(silu(acc1) * acc3) -> g_h (pre-rounded for gemm2)
    #pragma unroll
    for (int mi = 0; mi < 2; mi++) {
        int mr = m0 + wm * 32 + mi * 16;
        int r0 = mr + g, r1 = mr + g + 8;
        #pragma unroll
        for (int ni = 0; ni < 4; ni++) {
            int c = n0 + wn * 32 + ni * 8 + tg * 2;
            if (r0 < cnt) {
                size_t base = ((size_t)e * TMAX + r0) * FDIM + c;
                g_h[base    ] = f2tf_f(silu_f(acc1[mi][ni][0]) * acc3[mi][ni][0]);
                g_h[base + 1] = f2tf_f(silu_f(acc1[mi][ni][1]) * acc3[mi][ni][1]);
            }
            if (r1 < cnt) {
                size_t base = ((size_t)e * TMAX + r1) * FDIM + c;
                g_h[base    ] = f2tf_f(silu_f(acc1[mi][ni][2]) * acc3[mi][ni][2]);
                g_h[base + 1] = f2tf_f(silu_f(acc1[mi][ni][3]) * acc3[mi][ni][3]);
            }
        }
    }
}

// ---------------- kernel 3: grouped GEMM2  out += wt * (h @ w2^T) ------------
// tile 128(M) x 128(N) x 32(K), 3-stage cp.async pipeline, operands pre-rounded
#define SM2_A  (STAGES * 128 * 36)
#define SMEM2_BYTES (2 * SM2_A * 4)

__global__ __launch_bounds__(256, 2) void gemm2_kernel(
    const float* __restrict__ W2, float* __restrict__ out)
{
    const int e   = blockIdx.z;
    const int cnt = g_cnt[e];
    const int m0  = blockIdx.y * 128;
    if (m0 >= cnt) return;
    const int n0  = blockIdx.x * 128;

    extern __shared__ float smem[];
    float* sA = smem;
    float* sB = smem + SM2_A;
    #define A2(s,r,c)  sA[((s) * 128 + (r)) * 36 + (c)]
    #define B2(s,r,c)  sB[((s) * 128 + (r)) * 36 + (c)]

    const int tid  = threadIdx.x;
    const int lane = tid & 31, warp = tid >> 5;
    const int wm = warp & 3, wn = warp >> 2;
    const int g  = lane >> 2, tg = lane & 3;

    float acc[2][8][4] = {};

    const float* Ae  = g_h + ((size_t)e * TMAX + m0) * FDIM;
    const float* W2e = W2 + (size_t)e * HDIM * FDIM + (size_t)n0 * FDIM;
    const int c4 = (tid & 7) * 4;
    const int lrow = tid >> 3;
    const int nkt = FDIM / 32;

    #define LOAD2(s, kt) do {                                                    \
        int k0_ = (kt) * 32;                                                     \
        _Pragma("unroll")                                                        \
        for (int i_ = 0; i_ < 4; i_++) {                                         \
            int r_ = lrow + i_ * 32;                                             \
            cp16(&A2(s, r_, c4), Ae  + (size_t)r_ * FDIM + k0_ + c4);            \
            cp16(&B2(s, r_, c4), W2e + (size_t)r_ * FDIM + k0_ + c4);            \
        }                                                                        \
    } while (0)

    #pragma unroll
    for (int s = 0; s < STAGES - 1; s++) { LOAD2(s, s); CP_COMMIT(); }

    for (int it = 0; it < nkt; it++) {
        CP_WAIT(STAGES - 2);
        __syncthreads();

        int pf = it + STAGES - 1;
        if (pf < nkt) LOAD2((pf % STAGES), pf);
        CP_COMMIT();

        const int s = it % STAGES;
        #pragma unroll
        for (int kk = 0; kk < 32; kk += 8) {
            uint32_t a[2][4];
            #pragma unroll
            for (int mi = 0; mi < 2; mi++) {
                int mr = wm * 32 + mi * 16;
                a[mi][0] = __float_as_uint(A2(s, mr + g,     kk + tg    ));
                a[mi][1] = __float_as_uint(A2(s, mr + g + 8, kk + tg    ));
                a[mi][2] = __float_as_uint(A2(s, mr + g,     kk + tg + 4));
                a[mi][3] = __float_as_uint(A2(s, mr + g + 8, kk + tg + 4));
            }
            #pragma unroll
            for (int ni = 0; ni < 8; ni++) {
                int nc = wn * 64 + ni * 8;
                uint32_t b[2] = { __float_as_uint(B2(s, nc + g, kk + tg)),
                                  __float_as_uint(B2(s, nc + g, kk + tg + 4)) };
                #pragma unroll
                for (int mi = 0; mi < 2; mi++) {
                    mma_tf32(acc[mi][ni], a[mi], b);
                }
            }
        }
        __syncthreads();
    }

    // epilogue: out[tok] += wt * acc (exactly 2 commutative adds/elem)
    #pragma unroll
    for (int mi = 0; mi < 2; mi++) {
        int mr = m0 + wm * 32 + mi * 16;
        int r0 = mr + g, r1 = mr + g + 8;
        int tok0 = 0, tok1 = 0; float wt0 = 0.0f, wt1 = 0.0f;
        if (r0 < cnt) { tok0 = g_tok[e * TMAX + r0]; wt0 = g_wt[e * TMAX + r0]; }
        if (r1 < cnt) { tok1 = g_tok[e * TMAX + r1]; wt1 = g_wt[e * TMAX + r1]; }
        #pragma unroll
        for (int ni = 0; ni < 8; ni++) {
            int c = n0 + wn * 64 + ni * 8 + tg * 2;
            if (r0 < cnt) {
                atomicAdd(out + (size_t)tok0 * HDIM + c,     wt0 * acc[mi][ni][0]);
                atomicAdd(out + (size_t)tok0 * HDIM + c + 1, wt0 * acc[mi][ni][1]);
            }
            if (r1 < cnt) {
                atomicAdd(out + (size_t)tok1 * HDIM + c,     wt1 * acc[mi][ni][2]);
                atomicAdd(out + (size_t)tok1 * HDIM + c + 1, wt1 * acc[mi][ni][3]);
            }
        }
    }
}

// ---------------- launcher ---------------------------------------------------
extern "C" void kernel_launch(void* const* d_in, const int* in_sizes, int n_in,
                              void* d_out, int out_size) {
    const float* X  = (const float*)d_in[0];
    const float* GW = (const float*)d_in[1];
    const float* W1 = (const float*)d_in[2];
    const float* W2 = (const float*)d_in[3];
    const float* W3 = (const float*)d_in[4];
    float* out = (float*)d_out;

    int T = in_sizes[0] / HDIM;   // 4096
    if (T > TMAX) T = TMAX;

    cudaFuncSetAttribute(gemm1_kernel, cudaFuncAttributeMaxDynamicSharedMemorySize, SMEM1_BYTES);
    cudaFuncSetAttribute(gemm2_kernel, cudaFuncAttributeMaxDynamicSharedMemorySize, SMEM2_BYTES);

    zero_kernel<<<2048, 256>>>(out, out_size);

    // pre-round all GEMM operands to tf32 (RNA) once
    float *w1t, *w2t, *w3t, *xt;
    cudaGetSymbolAddress((void**)&w1t, g_w1t);
    cudaGetSymbolAddress((void**)&w2t, g_w2t);
    cudaGetSymbolAddress((void**)&w3t, g_w3t);
    cudaGetSymbolAddress((void**)&xt,  g_xt);
    convert_kernel<<<2048, 256>>>(W1, w1t, WELEM / 4);
    convert_kernel<<<2048, 256>>>(W2, w2t, WELEM / 4);
    convert_kernel<<<2048, 256>>>(W3, w3t, WELEM / 4);
    convert_kernel<<<512,  256>>>(X,  xt,  (T * HDIM) / 4);

    gate_kernel<<<T, 256>>>(X, GW);

    int mt = (T + 127) / 128;
    dim3 grid1(FDIM / 64, mt, NE);
    gemm1_kernel<<<grid1, 256, SMEM1_BYTES>>>(xt, w1t, w3t);

    dim3 grid2(HDIM / 128, mt, NE);
    gemm2_kernel<<<grid2, 256, SMEM2_BYTES>>>(w2t, out);
}

// round 6
// speedup vs baseline: 1.3094x; 1.0441x over previous
#include <cuda_runtime.h>
#include <cstdint>
#include <cstddef>

#define HDIM 2048
#define FDIM 7168
#define NE   8
#define TMAX 4096
#define STAGES 4
#define WELEM (NE * FDIM * HDIM)

// ---------------- device scratch ---------------------------------------------
__device__ int   g_cnt[NE];
__device__ int   g_tok[NE * TMAX];
__device__ float g_wt [NE * TMAX];
__device__ float g_h  [(size_t)NE * TMAX * FDIM];
__device__ float g_w1t[WELEM];
__device__ float g_w2t[WELEM];
__device__ float g_w3t[WELEM];
__device__ float g_xt [(size_t)TMAX * HDIM];

// ---------------- helpers ----------------------------------------------------
__device__ __forceinline__ uint32_t f2tf(float f) {
    uint32_t u;
    asm("cvt.rna.tf32.f32 %0, %1;" : "=r"(u) : "f"(f));
    return u;
}
__device__ __forceinline__ float f2tf_f(float f) { return __uint_as_float(f2tf(f)); }
__device__ __forceinline__ float silu_f(float x) { return x / (1.0f + __expf(-x)); }

__device__ __forceinline__ void mma_tf32(float c[4], const uint32_t a[4], const uint32_t b[2]) {
    asm volatile(
        "mma.sync.aligned.m16n8k8.row.col.f32.tf32.tf32.f32 "
        "{%0,%1,%2,%3}, {%4,%5,%6,%7}, {%8,%9}, {%0,%1,%2,%3};"
        : "+f"(c[0]), "+f"(c[1]), "+f"(c[2]), "+f"(c[3])
        : "r"(a[0]), "r"(a[1]), "r"(a[2]), "r"(a[3]), "r"(b[0]), "r"(b[1]));
}

__device__ __forceinline__ void cp16(void* smem, const float* g) {
    uint32_t sa = (uint32_t)__cvta_generic_to_shared(smem);
    asm volatile("cp.async.cg.shared.global [%0], [%1], 16;" :: "r"(sa), "l"(g));
}
#define CP_COMMIT()  asm volatile("cp.async.commit_group;")
#define CP_WAIT(N)   asm volatile("cp.async.wait_group %0;" :: "n"(N))

#define U(x) __float_as_uint(x)

// ---------------- kernel 0: zero out + counters ------------------------------
__global__ void zero_kernel(float* __restrict__ out, int n) {
    int idx = blockIdx.x * blockDim.x + threadIdx.x;
    if (idx < NE) g_cnt[idx] = 0;
    for (int i = idx; i < n; i += gridDim.x * blockDim.x) out[i] = 0.0f;
}

// ---------------- kernel 0b: tf32-RNA pre-round ------------------------------
__global__ void convert_kernel(const float* __restrict__ src, float* __restrict__ dst, int n4) {
    int idx = blockIdx.x * blockDim.x + threadIdx.x;
    const float4* s4 = (const float4*)src;
    float4* d4 = (float4*)dst;
    for (int i = idx; i < n4; i += gridDim.x * blockDim.x) {
        float4 v = s4[i];
        v.x = f2tf_f(v.x); v.y = f2tf_f(v.y); v.z = f2tf_f(v.z); v.w = f2tf_f(v.w);
        d4[i] = v;
    }
}

// ---------------- kernel 1: gating (top-2) -----------------------------------
__global__ void gate_kernel(const float* __restrict__ X, const float* __restrict__ GW) {
    const int t = blockIdx.x;
    __shared__ float xs[HDIM];
    __shared__ float logits[NE];
    const int tid = threadIdx.x;
    for (int i = tid; i < HDIM; i += 256) xs[i] = X[(size_t)t * HDIM + i];
    __syncthreads();
    const int warp = tid >> 5, lane = tid & 31;
    if (warp < NE) {
        const float* gw = GW + (size_t)warp * HDIM;
        float s = 0.0f;
        for (int i = lane; i < HDIM; i += 32) s += xs[i] * gw[i];
        #pragma unroll
        for (int o = 16; o; o >>= 1) s += __shfl_xor_sync(0xffffffffu, s, o);
        if (lane == 0) logits[warp] = s;
    }
    __syncthreads();
    if (tid == 0) {
        int i0 = 0; float l0 = logits[0];
        #pragma unroll
        for (int i = 1; i < NE; i++) if (logits[i] > l0) { l0 = logits[i]; i0 = i; }
        int i1 = -1; float l1 = -1e30f;
        #pragma unroll
        for (int i = 0; i < NE; i++) if (i != i0 && logits[i] > l1) { l1 = logits[i]; i1 = i; }
        float w0 = 1.0f / (1.0f + __expf(l1 - l0));
        float w1 = 1.0f - w0;
        int p0 = atomicAdd(&g_cnt[i0], 1);
        g_tok[i0 * TMAX + p0] = t; g_wt[i0 * TMAX + p0] = w0;
        int p1 = atomicAdd(&g_cnt[i1], 1);
        g_tok[i1 * TMAX + p1] = t; g_wt[i1 * TMAX + p1] = w1;
    }
}

// ---------------- kernel 2: GEMM1  h = silu(X@w1^T) * (X@w3^T) ---------------
// CTA tile 128(M) x 128(F), 8 warps 2(M)x4(N), warp tile 64x32 for BOTH w1,w3
#define SM1_A  (STAGES * 128 * 36)
#define SMEM1_BYTES (3 * SM1_A * 4)        // A + B1 + B3, 221184 B

__global__ __launch_bounds__(256, 1) void gemm1_kernel(
    const float* __restrict__ X,
    const float* __restrict__ W1,
    const float* __restrict__ W3)
{
    const int e   = blockIdx.z;
    const int cnt = g_cnt[e];
    const int m0  = blockIdx.x * 128;
    if (m0 >= cnt) return;
    const int n0  = blockIdx.y * 128;

    extern __shared__ float smem[];
    float* sA  = smem;
    float* sB1 = smem + SM1_A;
    float* sB3 = sB1 + SM1_A;
    #define A1(s,r,c)  sA [((s) * 128 + (r)) * 36 + (c)]
    #define B1(s,r,c)  sB1[((s) * 128 + (r)) * 36 + (c)]
    #define B3(s,r,c)  sB3[((s) * 128 + (r)) * 36 + (c)]

    const int tid  = threadIdx.x;
    const int lane = tid & 31, warp = tid >> 5;
    const int wm = warp & 1, wn = warp >> 1;    // 2(M) x 4(N)
    const int g  = lane >> 2, tg = lane & 3;

    float acc1[4][4][4] = {};
    float acc3[4][4][4] = {};

    const int*   tokp = g_tok + e * TMAX + m0;
    const float* W1e  = W1 + (size_t)e * FDIM * HDIM + (size_t)n0 * HDIM;
    const float* W3e  = W3 + (size_t)e * FDIM * HDIM + (size_t)n0 * HDIM;

    const int c4 = (tid & 7) * 4;
    const int r0 = tid >> 3;                    // 0..31
    int arow[4]; const float* aptr[4];
    #pragma unroll
    for (int i = 0; i < 4; i++) {
        arow[i] = r0 + i * 32;
        int tok = (m0 + arow[i] < cnt) ? tokp[arow[i]] : 0;
        aptr[i] = X + (size_t)tok * HDIM + c4;
    }
    const int nkt = HDIM / 32;   // 64

    #define LOAD1(s, kt) do {                                                   \
        int k0_ = (kt) * 32;                                                    \
        _Pragma("unroll")                                                       \
        for (int i_ = 0; i_ < 4; i_++) {                                        \
            int r_ = r0 + i_ * 32;                                              \
            cp16(&A1(s, r_, c4), aptr[i_] + k0_);                               \
            cp16(&B1(s, r_, c4), W1e + (size_t)r_ * HDIM + k0_ + c4);           \
            cp16(&B3(s, r_, c4), W3e + (size_t)r_ * HDIM + k0_ + c4);           \
        }                                                                       \
    } while (0)

    #pragma unroll
    for (int s = 0; s < STAGES - 1; s++) { LOAD1(s, s); CP_COMMIT(); }

    for (int it = 0; it < nkt; it++) {
        CP_WAIT(STAGES - 2);
        __syncthreads();

        int pf = it + STAGES - 1;
        if (pf < nkt) LOAD1((pf & (STAGES - 1)), pf);
        CP_COMMIT();

        const int s = it & (STAGES - 1);
        #pragma unroll
        for (int kk = 0; kk < 32; kk += 8) {
            uint32_t a[4][4];
            #pragma unroll
            for (int mi = 0; mi < 4; mi++) {
                int mr = wm * 64 + mi * 16;
                a[mi][0] = U(A1(s, mr + g,     kk + tg    ));
                a[mi][1] = U(A1(s, mr + g + 8, kk + tg    ));
                a[mi][2] = U(A1(s, mr + g,     kk + tg + 4));
                a[mi][3] = U(A1(s, mr + g + 8, kk + tg + 4));
            }
            #pragma unroll
            for (int ni = 0; ni < 4; ni++) {
                int nc = wn * 32 + ni * 8;
                uint32_t b1[2] = { U(B1(s, nc + g, kk + tg)), U(B1(s, nc + g, kk + tg + 4)) };
                uint32_t b3[2] = { U(B3(s, nc + g, kk + tg)), U(B3(s, nc + g, kk + tg + 4)) };
                #pragma unroll
                for (int mi = 0; mi < 4; mi++) {
                    mma_tf32(acc1[mi][ni], a[mi], b1);
                    mma_tf32(acc3[mi][ni], a[mi], b3);
                }
            }
        }
        __syncthreads();
    }

    // epilogue: h = tf32_round(silu(acc1) * acc3) -> g_h
    #pragma unroll
    for (int mi = 0; mi < 4; mi++) {
        int mr = m0 + wm * 64 + mi * 16;
        int ra = mr + g, rb = mr + g + 8;
        #pragma unroll
        for (int ni = 0; ni < 4; ni++) {
            int c = n0 + wn * 32 + ni * 8 + tg * 2;
            if (ra < cnt) {
                size_t base = ((size_t)e * TMAX + ra) * FDIM + c;
                g_h[base    ] = f2tf_f(silu_f(acc1[mi][ni][0]) * acc3[mi][ni][0]);
                g_h[base + 1] = f2tf_f(silu_f(acc1[mi][ni][1]) * acc3[mi][ni][1]);
            }
            if (rb < cnt) {
                size_t base = ((size_t)e * TMAX + rb) * FDIM + c;
                g_h[base    ] = f2tf_f(silu_f(acc1[mi][ni][2]) * acc3[mi][ni][2]);
                g_h[base + 1] = f2tf_f(silu_f(acc1[mi][ni][3]) * acc3[mi][ni][3]);
            }
        }
    }
}

// ---------------- kernel 3: GEMM2  out += wt * (h @ w2^T) --------------------
// CTA tile 128(M) x 256(N:H), 8 warps 2(M)x4(N), warp tile 64x64
#define SM2_A  (STAGES * 128 * 36)
#define SM2_B  (STAGES * 256 * 36)
#define SMEM2_BYTES ((SM2_A + SM2_B) * 4)   // 221184 B

__global__ __launch_bounds__(256, 1) void gemm2_kernel(
    const float* __restrict__ W2, float* __restrict__ out)
{
    const int e   = blockIdx.z;
    const int cnt = g_cnt[e];
    const int m0  = blockIdx.x * 128;
    if (m0 >= cnt) return;
    const int n0  = blockIdx.y * 256;

    extern __shared__ float smem[];
    float* sA = smem;
    float* sB = smem + SM2_A;
    #define A2(s,r,c)  sA[((s) * 128 + (r)) * 36 + (c)]
    #define B2(s,r,c)  sB[((s) * 256 + (r)) * 36 + (c)]

    const int tid  = threadIdx.x;
    const int lane = tid & 31, warp = tid >> 5;
    const int wm = warp & 1, wn = warp >> 1;    // 2(M) x 4(N)
    const int g  = lane >> 2, tg = lane & 3;

    float acc[4][8][4] = {};

    const float* Ae  = g_h + ((size_t)e * TMAX + m0) * FDIM;
    const float* W2e = W2 + (size_t)e * HDIM * FDIM + (size_t)n0 * FDIM;
    const int c4 = (tid & 7) * 4;
    const int r0 = tid >> 3;   // 0..31
    const int nkt = FDIM / 32; // 224

    #define LOAD2(s, kt) do {                                                    \
        int k0_ = (kt) * 32;                                                     \
        _Pragma("unroll")                                                        \
        for (int i_ = 0; i_ < 4; i_++) {                                         \
            int r_ = r0 + i_ * 32;                                               \
            cp16(&A2(s, r_, c4), Ae + (size_t)r_ * FDIM + k0_ + c4);             \
        }                                                                        \
        _Pragma("unroll")                                                        \
        for (int i_ = 0; i_ < 8; i_++) {                                         \
            int r_ = r0 + i_ * 32;                                               \
            cp16(&B2(s, r_, c4), W2e + (size_t)r_ * FDIM + k0_ + c4);            \
        }                                                                        \
    } while (0)

    #pragma unroll
    for (int s = 0; s < STAGES - 1; s++) { LOAD2(s, s); CP_COMMIT(); }

    for (int it = 0; it < nkt; it++) {
        CP_WAIT(STAGES - 2);
        __syncthreads();

        int pf = it + STAGES - 1;
        if (pf < nkt) LOAD2((pf & (STAGES - 1)), pf);
        CP_COMMIT();

        const int s = it & (STAGES - 1);
        #pragma unroll
        for (int kk = 0; kk < 32; kk += 8) {
            uint32_t a[4][4];
            #pragma unroll
            for (int mi = 0; mi < 4; mi++) {
                int mr = wm * 64 + mi * 16;
                a[mi][0] = U(A2(s, mr + g,     kk + tg    ));
                a[mi][1] = U(A2(s, mr + g + 8, kk + tg    ));
                a[mi][2] = U(A2(s, mr + g,     kk + tg + 4));
                a[mi][3] = U(A2(s, mr + g + 8, kk + tg + 4));
            }
            #pragma unroll
            for (int ni = 0; ni < 8; ni++) {
                int nc = wn * 64 + ni * 8;
                uint32_t b[2] = { U(B2(s, nc + g, kk + tg)), U(B2(s, nc + g, kk + tg + 4)) };
                #pragma unroll
                for (int mi = 0; mi < 4; mi++) {
                    mma_tf32(acc[mi][ni], a[mi], b);
                }
            }
        }
        __syncthreads();
    }

    // epilogue: out[tok] += wt * acc (exactly 2 commutative adds/elem)
    #pragma unroll
    for (int mi = 0; mi < 4; mi++) {
        int mr = m0 + wm * 64 + mi * 16;
        int ra = mr + g, rb = mr + g + 8;
        int tok0 = 0, tok1 = 0; float wt0 = 0.0f, wt1 = 0.0f;
        if (ra < cnt) { tok0 = g_tok[e * TMAX + ra]; wt0 = g_wt[e * TMAX + ra]; }
        if (rb < cnt) { tok1 = g_tok[e * TMAX + rb]; wt1 = g_wt[e * TMAX + rb]; }
        #pragma unroll
        for (int ni = 0; ni < 8; ni++) {
            int c = n0 + wn * 64 + ni * 8 + tg * 2;
            if (ra < cnt) {
                atomicAdd(out + (size_t)tok0 * HDIM + c,     wt0 * acc[mi][ni][0]);
                atomicAdd(out + (size_t)tok0 * HDIM + c + 1, wt0 * acc[mi][ni][1]);
            }
            if (rb < cnt) {
                atomicAdd(out + (size_t)tok1 * HDIM + c,     wt1 * acc[mi][ni][2]);
                atomicAdd(out + (size_t)tok1 * HDIM + c + 1, wt1 * acc[mi][ni][3]);
            }
        }
    }
}

// ---------------- launcher ---------------------------------------------------
extern "C" void kernel_launch(void* const* d_in, const int* in_sizes, int n_in,
                              void* d_out, int out_size) {
    const float* X  = (const float*)d_in[0];
    const float* GW = (const float*)d_in[1];
    const float* W1 = (const float*)d_in[2];
    const float* W2 = (const float*)d_in[3];
    const float* W3 = (const float*)d_in[4];
    float* out = (float*)d_out;

    int T = in_sizes[0] / HDIM;   // 4096
    if (T > TMAX) T = TMAX;

    cudaFuncSetAttribute(gemm1_kernel, cudaFuncAttributeMaxDynamicSharedMemorySize, SMEM1_BYTES);
    cudaFuncSetAttribute(gemm2_kernel, cudaFuncAttributeMaxDynamicSharedMemorySize, SMEM2_BYTES);

    zero_kernel<<<2048, 256>>>(out, out_size);

    float *w1t, *w2t, *w3t, *xt;
    cudaGetSymbolAddress((void**)&w1t, g_w1t);
    cudaGetSymbolAddress((void**)&w2t, g_w2t);
    cudaGetSymbolAddress((void**)&w3t, g_w3t);
    cudaGetSymbolAddress((void**)&xt,  g_xt);
    convert_kernel<<<2048, 256>>>(W1, w1t, WELEM / 4);
    convert_kernel<<<2048, 256>>>(W2, w2t, WELEM / 4);
    convert_kernel<<<2048, 256>>>(W3, w3t, WELEM / 4);
    convert_kernel<<<512,  256>>>(X,  xt,  (T * HDIM) / 4);

    gate_kernel<<<T, 256>>>(X, GW);

    int mt = (T + 127) / 128;
    dim3 grid1(mt, FDIM / 128, NE);     // x = M fastest -> weight tiles shared in L2
    gemm1_kernel<<<grid1, 256, SMEM1_BYTES>>>(xt, w1t, w3t);

    dim3 grid2(mt, HDIM / 256, NE);
    gemm2_kernel<<<grid2, 256, SMEM2_BYTES>>>(w2t, out);
}